// round 5
// baseline (speedup 1.0000x reference)
#include <cuda_runtime.h>
#include <cstdint>

// Problem constants
#define Bn 8
#define Cn 256
#define Hn 96
#define Wn 128
#define Dd 4
#define NS 9      // 2*D+1
#define Qn 81     // NS*NS
#define HW (Hn*Wn)

// Tiling: 1 output row per block, 2 blocks/SM co-resident
#define RX 4                  // x pixels per thread
#define XG (Wn/RX)            // 32 x-groups
#define NTHREADS (XG*NS)      // 288
#define CC 8                  // channels per smem chunk
#define NCHUNK (Cn/CC)        // 32
#define FBW (Wn + 2*Dd)       // 136
#define FBH (2*Dd + 1)        // 9 halo rows (TY=1)
#define VW (RX + 2*Dd)        // 12 window floats per thread

#define FA_FLOATS (CC*Wn)             // 1024
#define FB_FLOATS (CC*FBH*FBW)        // 9792
#define STAGE_FLOATS (FA_FLOATS + FB_FLOATS)   // 10816
#define SMEM_BYTES (2*STAGE_FLOATS*4)          // 86528 (x2 blocks = 173KB/SM)

#define FA_SLOTS (CC*(Wn/4))          // 256
#define FB_SLOTS (CC*FBH*(FBW/4))     // 2448
#define TOT_SLOTS (FA_SLOTS+FB_SLOTS) // 2704
#define MAXSL 10                      // ceil(2704/288)

// Per-pixel inverse norms (scratch)
__device__ float g_inva[Bn*HW];
__device__ float g_invb[Bn*HW];

// ---------------------------------------------------------------------------
__device__ __forceinline__ void cp16(uint32_t saddr, const float* g, int nbytes) {
    asm volatile("cp.async.cg.shared.global [%0], [%1], 16, %2;"
                 :: "r"(saddr), "l"(g), "r"(nbytes));
}

// ---------------------------------------------------------------------------
// Pass 1: per-pixel inverse L2 norms (HBM-bound, ~37us)
// ---------------------------------------------------------------------------
__global__ void norm_kernel(const float* __restrict__ fa,
                            const float* __restrict__ fb) {
    int pix = blockIdx.x * blockDim.x + threadIdx.x;
    int b   = blockIdx.y;
    const float* pa = fa + (size_t)b * Cn * HW + pix;
    const float* pb = fb + (size_t)b * Cn * HW + pix;
    float sa = 0.f, sb = 0.f;
#pragma unroll 8
    for (int c = 0; c < Cn; c++) {
        float va = pa[(size_t)c * HW];
        float vb = pb[(size_t)c * HW];
        sa = fmaf(va, va, sa);
        sb = fmaf(vb, vb, sb);
    }
    g_inva[b * HW + pix] = 1.0f / fmaxf(sqrtf(sa), 1e-12f);
    g_invb[b * HW + pix] = 1.0f / fmaxf(sqrtf(sb), 1e-12f);
}

// ---------------------------------------------------------------------------
// Pass 2: correlation. Block = (b, 1 row, full W), 288 threads, 2 blocks/SM.
// Thread = (4 x-pixels, one dy) -> 36 scalar accumulators.
// Per channel: 1 LDS.128 fa + 3 LDS.128 fb + 36 FFMA.
// 2-stage cp.async pipeline (CC=8), balanced loader slots.
// ---------------------------------------------------------------------------
__global__ void __launch_bounds__(NTHREADS, 2)
corr_kernel(const float* __restrict__ fa,
            const float* __restrict__ fb,
            float* __restrict__ out) {
    extern __shared__ float smem[];

    const int b   = blockIdx.y;
    const int y0  = blockIdx.x;
    const int tid = threadIdx.x;

    const int dy = tid / XG;                 // 0..8 (one dy per warp)
    const int xg = tid % XG;                 // 0..31
    const int x0 = xg * RX;

    const size_t baseA = (size_t)b * Cn * HW;

    // ---- balanced loader slot descriptors (hoisted) ----
    int ld_g[MAXSL], ld_s[MAXSL], ld_nb[MAXSL];
#pragma unroll
    for (int si = 0; si < MAXSL; si++) {
        int slot = tid + si * NTHREADS;
        ld_g[si] = 0; ld_s[si] = 0; ld_nb[si] = -1;   // -1 = dead slot
        if (slot < TOT_SLOTS) {
            if (slot < FA_SLOTS) {
                int cc = slot / (Wn / 4);
                int x4 = slot % (Wn / 4);
                ld_nb[si] = 16;
                ld_g[si]  = cc * HW + y0 * Wn + x4 * 4;
                ld_s[si]  = cc * Wn + x4 * 4;
                ld_g[si] |= (1 << 30);       // tag: fa source (bit30 spare; HW<2^23)
            } else {
                int t  = slot - FA_SLOTS;
                int cc = t / (FBH * (FBW / 4));
                int u  = t % (FBH * (FBW / 4));
                int hr = u / (FBW / 4);
                int k  = u % (FBW / 4);
                int yy = y0 - Dd + hr;
                bool valid = (yy >= 0) && (yy < Hn) && (k >= 1) && (k <= Wn / 4);
                ld_nb[si] = valid ? 16 : 0;  // zfill for halo/OOB
                int yyc = min(max(yy, 0), Hn - 1);
                int kc  = min(max(k, 1), Wn / 4);
                ld_g[si] = cc * HW + yyc * Wn + kc * 4 - 4;
                ld_s[si] = FA_FLOATS + cc * (FBH * FBW) + hr * FBW + k * 4;
            }
        }
    }

    const uint32_t smem_u = (uint32_t)__cvta_generic_to_shared(smem);
    const float* gA = fa + baseA;
    const float* gB = fb + baseA;

    auto prefetch = [&](int c0, int st) {
        const uint32_t sbase = smem_u + (uint32_t)(st * STAGE_FLOATS * 4);
        const int cofs = c0 * HW;
#pragma unroll
        for (int si = 0; si < MAXSL; si++) {
            if (ld_nb[si] >= 0) {
                bool isA = (ld_g[si] & (1 << 30)) != 0;
                int gofs = (ld_g[si] & ~(1 << 30)) + cofs;
                const float* src = (isA ? gA : gB) + gofs;
                cp16(sbase + (uint32_t)(ld_s[si] * 4), src, ld_nb[si]);
            }
        }
    };

    float acc[NS][RX];
#pragma unroll
    for (int d = 0; d < NS; d++)
#pragma unroll
        for (int i = 0; i < RX; i++) acc[d][i] = 0.f;

    const int ofsA = x0;
    const int ofsB = dy * FBW + x0;

    // ---- pipeline prologue ----
    prefetch(0, 0);
    asm volatile("cp.async.commit_group;");

    int st = 0;
    for (int ch = 0; ch < NCHUNK; ch++) {
        asm volatile("cp.async.wait_group 0;");   // chunk ch landed
        __syncthreads();                          // all warps done with st^1
        if (ch + 1 < NCHUNK) prefetch((ch + 1) * CC, st ^ 1);
        asm volatile("cp.async.commit_group;");

        const float* s_fa = smem + st * STAGE_FLOATS;
        const float* s_fb = s_fa + FA_FLOATS;
#pragma unroll
        for (int cc = 0; cc < CC; cc++) {
            const float* fap = s_fa + cc * Wn + ofsA;
            const float* fbp = s_fb + cc * (FBH * FBW) + ofsB;
            float4 A  = *(const float4*)(fap);
            float4 V0 = *(const float4*)(fbp);
            float4 V1 = *(const float4*)(fbp + 4);
            float4 V2 = *(const float4*)(fbp + 8);
            float a[RX] = {A.x, A.y, A.z, A.w};
            float v[VW] = {V0.x, V0.y, V0.z, V0.w, V1.x, V1.y, V1.z, V1.w,
                           V2.x, V2.y, V2.z, V2.w};
#pragma unroll
            for (int dx = 0; dx < NS; dx++)
#pragma unroll
                for (int i = 0; i < RX; i++)
                    acc[dx][i] = fmaf(a[i], v[dx + i], acc[dx][i]);
        }
        st ^= 1;
    }

    // ---- epilogue: scale by inverse norms, write float4 per dx ----
    const int y = y0;
    float ia[RX];
#pragma unroll
    for (int i = 0; i < RX; i++) ia[i] = g_inva[b * HW + y * Wn + x0 + i];

    const int sy = y + dy - Dd;
    const bool rowok = (unsigned)sy < (unsigned)Hn;
    float ib[VW];
#pragma unroll
    for (int k = 0; k < VW; k++) {
        int sx = x0 + k - Dd;
        ib[k] = (rowok && (unsigned)sx < (unsigned)Wn)
                    ? g_invb[b * HW + sy * Wn + sx] : 0.f;
        // raw acc is exactly 0 for OOB (zfill halo), so ib=0 is safe
    }

#pragma unroll
    for (int dx = 0; dx < NS; dx++) {
        float4 o;
        o.x = acc[dx][0] * ia[0] * ib[dx + 0];
        o.y = acc[dx][1] * ia[1] * ib[dx + 1];
        o.z = acc[dx][2] * ia[2] * ib[dx + 2];
        o.w = acc[dx][3] * ia[3] * ib[dx + 3];
        const int q = dy * NS + dx;
        *(float4*)(out + ((size_t)(b * Qn + q) * Hn + y) * Wn + x0) = o;
    }
}

// ---------------------------------------------------------------------------
extern "C" void kernel_launch(void* const* d_in, const int* in_sizes, int n_in,
                              void* d_out, int out_size) {
    const float* fa = (const float*)d_in[0];
    const float* fb = (const float*)d_in[1];
    float* out = (float*)d_out;

    norm_kernel<<<dim3(HW / 256, Bn), 256>>>(fa, fb);

    cudaFuncSetAttribute(corr_kernel,
                         cudaFuncAttributeMaxDynamicSharedMemorySize,
                         SMEM_BYTES);
    corr_kernel<<<dim3(Hn, Bn), NTHREADS, SMEM_BYTES>>>(fa, fb, out);
}

// round 6
// speedup vs baseline: 1.0865x; 1.0865x over previous
#include <cuda_runtime.h>
#include <cstdint>

// Problem constants
#define Bn 8
#define Cn 256
#define Hn 96
#define Wn 128
#define Dd 4
#define NS 9      // 2*D+1
#define Qn 81     // NS*NS
#define HW (Hn*Wn)

// Tiling: 3 output rows per block, 864 threads (27 warps/SM)
#define TY 3                  // y rows per block
#define RX 4                  // x pixels per thread
#define XG (Wn/RX)            // 32 x-groups
#define NTHREADS (TY*XG*NS)   // 864
#define CC 8                  // channels per smem chunk
#define NCHUNK (Cn/CC)        // 32
#define NSTAGES 3
#define FBW (Wn + 2*Dd)       // 136
#define FBH (TY + 2*Dd)       // 11 halo rows
#define VW (RX + 2*Dd)        // 12 window floats per thread

#define FA_FLOATS (CC*TY*Wn)          // 3072
#define FB_FLOATS (CC*FBH*FBW)        // 11968
#define STAGE_FLOATS (FA_FLOATS + FB_FLOATS)   // 15040
#define SMEM_BYTES (NSTAGES*STAGE_FLOATS*4)    // 180480

#define FA_SLOTS (FA_FLOATS/4)        // 768
#define FB_SLOTS (FB_FLOATS/4)        // 2992
#define TOT_SLOTS (FA_SLOTS+FB_SLOTS) // 3760
#define MAXSL 5                       // ceil(3760/864)

// Per-pixel inverse norms (scratch)
__device__ float g_inva[Bn*HW];
__device__ float g_invb[Bn*HW];

// ---------------------------------------------------------------------------
__device__ __forceinline__ void cp16(uint32_t saddr, const float* g, int nbytes) {
    asm volatile("cp.async.cg.shared.global [%0], [%1], 16, %2;"
                 :: "r"(saddr), "l"(g), "r"(nbytes));
}

// ---------------------------------------------------------------------------
// Pass 1: per-pixel inverse L2 norms (HBM-bound, ~37us)
// ---------------------------------------------------------------------------
__global__ void norm_kernel(const float* __restrict__ fa,
                            const float* __restrict__ fb) {
    int pix = blockIdx.x * blockDim.x + threadIdx.x;
    int b   = blockIdx.y;
    const float* pa = fa + (size_t)b * Cn * HW + pix;
    const float* pb = fb + (size_t)b * Cn * HW + pix;
    float sa = 0.f, sb = 0.f;
#pragma unroll 8
    for (int c = 0; c < Cn; c++) {
        float va = pa[(size_t)c * HW];
        float vb = pb[(size_t)c * HW];
        sa = fmaf(va, va, sa);
        sb = fmaf(vb, vb, sb);
    }
    g_inva[b * HW + pix] = 1.0f / fmaxf(sqrtf(sa), 1e-12f);
    g_invb[b * HW + pix] = 1.0f / fmaxf(sqrtf(sb), 1e-12f);
}

// ---------------------------------------------------------------------------
// Pass 2: correlation. Block = (b, 3 rows, full W), 864 threads, 27 warps/SM.
// Thread = (yl, 4 x-pixels, one dy) -> 36 scalar accumulators.
// Per channel: 1 LDS.128 fa + 3 LDS.128 fb + 36 FFMA.
// 3-stage cp.async pipeline (CC=8), balanced loader slots.
// ---------------------------------------------------------------------------
__global__ void __launch_bounds__(NTHREADS, 1)
corr_kernel(const float* __restrict__ fa,
            const float* __restrict__ fb,
            float* __restrict__ out) {
    extern __shared__ float smem[];

    const int b   = blockIdx.y;
    const int y0  = blockIdx.x * TY;
    const int tid = threadIdx.x;

    const int dy = tid / (TY * XG);          // 0..8 (uniform per warp)
    const int r  = tid % (TY * XG);
    const int yl = r / XG;                   // 0..2 (uniform per warp)
    const int xg = r % XG;                   // 0..31
    const int x0 = xg * RX;

    const size_t baseA = (size_t)b * Cn * HW;

    // ---- balanced loader slot descriptors (hoisted, compact) ----
    // ld_g: bits[0:29] global float offset (within one channel set), bit30 = fa tag
    // ld_nb: -1 dead, 0 zfill (halo/OOB), 16 real load
    int ld_g[MAXSL], ld_s[MAXSL], ld_nb[MAXSL];
#pragma unroll
    for (int si = 0; si < MAXSL; si++) {
        int slot = tid + si * NTHREADS;
        ld_g[si] = 0; ld_s[si] = 0; ld_nb[si] = -1;
        if (slot < TOT_SLOTS) {
            if (slot < FA_SLOTS) {
                int cc = slot / (TY * (Wn / 4));
                int rr = slot % (TY * (Wn / 4));
                int yy = rr / (Wn / 4);
                int x4 = rr % (Wn / 4);
                ld_nb[si] = 16;
                ld_g[si]  = (cc * HW + (y0 + yy) * Wn + x4 * 4) | (1 << 30);
                ld_s[si]  = cc * (TY * Wn) + yy * Wn + x4 * 4;
            } else {
                int t  = slot - FA_SLOTS;
                int cc = t / (FBH * (FBW / 4));
                int u  = t % (FBH * (FBW / 4));
                int hr = u / (FBW / 4);
                int k  = u % (FBW / 4);
                int yy = y0 - Dd + hr;
                bool valid = (yy >= 0) && (yy < Hn) && (k >= 1) && (k <= Wn / 4);
                ld_nb[si] = valid ? 16 : 0;          // zfill for halo/OOB
                int yyc = min(max(yy, 0), Hn - 1);
                int kc  = min(max(k, 1), Wn / 4);
                ld_g[si] = cc * HW + yyc * Wn + kc * 4 - 4;
                ld_s[si] = FA_FLOATS + cc * (FBH * FBW) + hr * FBW + k * 4;
            }
        }
    }

    const uint32_t smem_u = (uint32_t)__cvta_generic_to_shared(smem);
    const float* gA = fa + baseA;
    const float* gB = fb + baseA;

    auto prefetch = [&](int c0, int st) {
        const uint32_t sbase = smem_u + (uint32_t)(st * STAGE_FLOATS * 4);
        const int cofs = c0 * HW;
#pragma unroll
        for (int si = 0; si < MAXSL; si++) {
            if (ld_nb[si] >= 0) {
                bool isA = (ld_g[si] & (1 << 30)) != 0;
                int gofs = (ld_g[si] & ~(1 << 30)) + cofs;
                const float* src = (isA ? gA : gB) + gofs;
                cp16(sbase + (uint32_t)(ld_s[si] * 4), src, ld_nb[si]);
            }
        }
    };

    float acc[NS][RX];
#pragma unroll
    for (int d = 0; d < NS; d++)
#pragma unroll
        for (int i = 0; i < RX; i++) acc[d][i] = 0.f;

    const int ofsA = yl * Wn + x0;
    const int ofsB = (yl + dy) * FBW + x0;

    // ---- pipeline prologue: 2 chunks in flight ----
    prefetch(0, 0);
    asm volatile("cp.async.commit_group;");
    prefetch(CC, 1);
    asm volatile("cp.async.commit_group;");

    int cs = 0;  // compute stage
    for (int ch = 0; ch < NCHUNK; ch++) {
        asm volatile("cp.async.wait_group 1;");   // chunk ch landed
        __syncthreads();                          // stage cs+2 reusable
        int ps = cs + 2; if (ps >= NSTAGES) ps -= NSTAGES;
        if (ch + 2 < NCHUNK) prefetch((ch + 2) * CC, ps);
        asm volatile("cp.async.commit_group;");   // keep group count in step

        const float* s_fa = smem + cs * STAGE_FLOATS;
        const float* s_fb = s_fa + FA_FLOATS;
#pragma unroll
        for (int cc = 0; cc < CC; cc++) {
            const float* fap = s_fa + cc * (TY * Wn) + ofsA;
            const float* fbp = s_fb + cc * (FBH * FBW) + ofsB;
            float4 A  = *(const float4*)(fap);
            float4 V0 = *(const float4*)(fbp);
            float4 V1 = *(const float4*)(fbp + 4);
            float4 V2 = *(const float4*)(fbp + 8);
            float a[RX] = {A.x, A.y, A.z, A.w};
            float v[VW] = {V0.x, V0.y, V0.z, V0.w, V1.x, V1.y, V1.z, V1.w,
                           V2.x, V2.y, V2.z, V2.w};
#pragma unroll
            for (int dx = 0; dx < NS; dx++)
#pragma unroll
                for (int i = 0; i < RX; i++)
                    acc[dx][i] = fmaf(a[i], v[dx + i], acc[dx][i]);
        }
        cs++; if (cs >= NSTAGES) cs = 0;
    }

    // ---- epilogue: scale by inverse norms, write float4 per dx ----
    const int y = y0 + yl;
    float ia[RX];
#pragma unroll
    for (int i = 0; i < RX; i++) ia[i] = g_inva[b * HW + y * Wn + x0 + i];

    const int sy = y + dy - Dd;
    const bool rowok = (unsigned)sy < (unsigned)Hn;
    float ib[VW];
#pragma unroll
    for (int k = 0; k < VW; k++) {
        int sx = x0 + k - Dd;
        ib[k] = (rowok && (unsigned)sx < (unsigned)Wn)
                    ? g_invb[b * HW + sy * Wn + sx] : 0.f;
        // raw acc is exactly 0 for OOB (zfill halo), so ib=0 is safe
    }

#pragma unroll
    for (int dx = 0; dx < NS; dx++) {
        float4 o;
        o.x = acc[dx][0] * ia[0] * ib[dx + 0];
        o.y = acc[dx][1] * ia[1] * ib[dx + 1];
        o.z = acc[dx][2] * ia[2] * ib[dx + 2];
        o.w = acc[dx][3] * ia[3] * ib[dx + 3];
        const int q = dy * NS + dx;
        *(float4*)(out + ((size_t)(b * Qn + q) * Hn + y) * Wn + x0) = o;
    }
}

// ---------------------------------------------------------------------------
extern "C" void kernel_launch(void* const* d_in, const int* in_sizes, int n_in,
                              void* d_out, int out_size) {
    const float* fa = (const float*)d_in[0];
    const float* fb = (const float*)d_in[1];
    float* out = (float*)d_out;

    norm_kernel<<<dim3(HW / 256, Bn), 256>>>(fa, fb);

    cudaFuncSetAttribute(corr_kernel,
                         cudaFuncAttributeMaxDynamicSharedMemorySize,
                         SMEM_BYTES);
    corr_kernel<<<dim3(Hn / TY, Bn), NTHREADS, SMEM_BYTES>>>(fa, fb, out);
}

// round 7
// speedup vs baseline: 1.1300x; 1.0401x over previous
#include <cuda_runtime.h>
#include <cstdint>

// Problem constants
#define Bn 8
#define Cn 256
#define Hn 96
#define Wn 128
#define Dd 4
#define NS 9      // 2*D+1
#define Qn 81     // NS*NS
#define HW (Hn*Wn)

// Tiling: 2 rows per block, 576 threads, CC=16, 2 smem stages
#define TY 2
#define RX 4
#define XG (Wn/RX)            // 32
#define NTHREADS (TY*XG*NS)   // 576
#define CC 16
#define NCHUNK (Cn/CC)        // 16
#define FBW (Wn + 2*Dd)       // 136
#define FBH (TY + 2*Dd)       // 10
#define VW (RX + 2*Dd)        // 12

#define FA_FLOATS (CC*TY*Wn)          // 4096
#define FB_FLOATS (CC*FBH*FBW)        // 21760
#define STAGE_FLOATS (FA_FLOATS + FB_FLOATS)   // 25856
#define SMEM_BYTES (2*STAGE_FLOATS*4)          // 206848

// per-channel loader slots: fa 64, fb 340 -> 404 (<576, one per thread)
#define FA_SL (TY*(Wn/4))             // 64
#define FB_SL (FBH*(FBW/4))           // 340
#define TOT_SL (FA_SL+FB_SL)          // 404

// Per-pixel inverse norms (scratch)
__device__ float g_inva[Bn*HW];
__device__ float g_invb[Bn*HW];

// ---------------------------------------------------------------------------
__device__ __forceinline__ void cp16(uint32_t saddr, const float* g, int nbytes) {
    asm volatile("cp.async.cg.shared.global [%0], [%1], 16, %2;"
                 :: "r"(saddr), "l"(g), "r"(nbytes));
}

// ---------------------------------------------------------------------------
// Pass 1: per-pixel inverse L2 norms (HBM-bound)
// ---------------------------------------------------------------------------
__global__ void norm_kernel(const float* __restrict__ fa,
                            const float* __restrict__ fb) {
    int pix = blockIdx.x * blockDim.x + threadIdx.x;
    int b   = blockIdx.y;
    const float* pa = fa + (size_t)b * Cn * HW + pix;
    const float* pb = fb + (size_t)b * Cn * HW + pix;
    float sa = 0.f, sb = 0.f;
#pragma unroll 16
    for (int c = 0; c < Cn; c++) {
        float va = pa[(size_t)c * HW];
        float vb = pb[(size_t)c * HW];
        sa = fmaf(va, va, sa);
        sb = fmaf(vb, vb, sb);
    }
    g_inva[b * HW + pix] = 1.0f / fmaxf(sqrtf(sa), 1e-12f);
    g_invb[b * HW + pix] = 1.0f / fmaxf(sqrtf(sb), 1e-12f);
}

// ---------------------------------------------------------------------------
// Pass 2: correlation. 576 threads, CC=16, 2-stage cp.async pipeline,
// explicit register double-buffering of the per-channel LDS->FFMA chain.
// ---------------------------------------------------------------------------
__global__ void __launch_bounds__(NTHREADS, 1)
corr_kernel(const float* __restrict__ fa,
            const float* __restrict__ fb,
            float* __restrict__ out) {
    extern __shared__ float smem[];

    const int b   = blockIdx.y;
    const int y0  = blockIdx.x * TY;
    const int tid = threadIdx.x;

    const int dy = tid / (TY * XG);          // 0..8 (uniform per warp)
    const int r  = tid % (TY * XG);
    const int yl = r / XG;                   // 0..1
    const int xg = r % XG;                   // 0..31
    const int x0 = xg * RX;

    const size_t baseA = (size_t)b * Cn * HW;

    // ---- loader: each thread owns at most ONE slot per channel ----
    const float* ld_ptr = nullptr;   // global base for this slot (channel 0)
    int ld_s = 0;        // smem float offset within stage (channel 0)
    int ld_sstr = 0;     // smem float stride per channel
    int ld_nb = -1;      // -1 dead, 0 zfill, 16 real
    if (tid < FA_SL) {
        int yy = tid / (Wn / 4);
        int x4 = tid % (Wn / 4);
        ld_nb   = 16;
        ld_ptr  = fa + baseA + (y0 + yy) * Wn + x4 * 4;
        ld_s    = yy * Wn + x4 * 4;
        ld_sstr = TY * Wn;
    } else if (tid < TOT_SL) {
        int u  = tid - FA_SL;
        int hr = u / (FBW / 4);
        int k  = u % (FBW / 4);
        int yy = y0 - Dd + hr;
        bool valid = (yy >= 0) && (yy < Hn) && (k >= 1) && (k <= Wn / 4);
        ld_nb   = valid ? 16 : 0;            // zfill halo/OOB
        int yyc = min(max(yy, 0), Hn - 1);
        int kc  = min(max(k, 1), Wn / 4);
        ld_ptr  = fb + baseA + yyc * Wn + kc * 4 - 4;
        ld_s    = FA_FLOATS + hr * FBW + k * 4;
        ld_sstr = FBH * FBW;
    }

    const uint32_t smem_u = (uint32_t)__cvta_generic_to_shared(smem);

    auto prefetch = [&](int c0, int st) {
        if (ld_nb >= 0) {
            const uint32_t sb = smem_u + (uint32_t)((st * STAGE_FLOATS + ld_s) * 4);
            const float* g = ld_ptr + (size_t)c0 * HW;
#pragma unroll
            for (int cc = 0; cc < CC; cc++)
                cp16(sb + (uint32_t)(cc * ld_sstr * 4), g + (size_t)cc * HW, ld_nb);
        }
    };

    float acc[NS][RX];
#pragma unroll
    for (int d = 0; d < NS; d++)
#pragma unroll
        for (int i = 0; i < RX; i++) acc[d][i] = 0.f;

    const int ofsA = yl * Wn + x0;
    const int ofsB = (yl + dy) * FBW + x0;

    // ---- pipeline prologue ----
    prefetch(0, 0);
    asm volatile("cp.async.commit_group;");

    int st = 0;
    for (int ch = 0; ch < NCHUNK; ch++) {
        asm volatile("cp.async.wait_group 0;");   // chunk ch landed
        __syncthreads();                          // st^1 free (prev compute done)
        if (ch + 1 < NCHUNK) prefetch((ch + 1) * CC, st ^ 1);
        asm volatile("cp.async.commit_group;");

        const float* s_fa = smem + st * STAGE_FLOATS;
        const float* s_fb = s_fa + FA_FLOATS;

        // explicit register double-buffer across channels
        float4 A, V0, V1, V2;
        A  = *(const float4*)(s_fa + ofsA);
        V0 = *(const float4*)(s_fb + ofsB);
        V1 = *(const float4*)(s_fb + ofsB + 4);
        V2 = *(const float4*)(s_fb + ofsB + 8);

#pragma unroll
        for (int cc = 0; cc < CC; cc++) {
            float4 An, V0n, V1n, V2n;
            if (cc + 1 < CC) {
                const float* fap = s_fa + (cc + 1) * (TY * Wn) + ofsA;
                const float* fbp = s_fb + (cc + 1) * (FBH * FBW) + ofsB;
                An  = *(const float4*)(fap);
                V0n = *(const float4*)(fbp);
                V1n = *(const float4*)(fbp + 4);
                V2n = *(const float4*)(fbp + 8);
            }
            float a[RX] = {A.x, A.y, A.z, A.w};
            float v[VW] = {V0.x, V0.y, V0.z, V0.w, V1.x, V1.y, V1.z, V1.w,
                           V2.x, V2.y, V2.z, V2.w};
#pragma unroll
            for (int dx = 0; dx < NS; dx++)
#pragma unroll
                for (int i = 0; i < RX; i++)
                    acc[dx][i] = fmaf(a[i], v[dx + i], acc[dx][i]);
            if (cc + 1 < CC) { A = An; V0 = V0n; V1 = V1n; V2 = V2n; }
        }
        st ^= 1;
    }

    // ---- epilogue: scale by inverse norms, write float4 per dx ----
    const int y = y0 + yl;
    float ia[RX];
#pragma unroll
    for (int i = 0; i < RX; i++) ia[i] = g_inva[b * HW + y * Wn + x0 + i];

    const int sy = y + dy - Dd;
    const bool rowok = (unsigned)sy < (unsigned)Hn;
    float ib[VW];
#pragma unroll
    for (int k = 0; k < VW; k++) {
        int sx = x0 + k - Dd;
        ib[k] = (rowok && (unsigned)sx < (unsigned)Wn)
                    ? g_invb[b * HW + sy * Wn + sx] : 0.f;
        // raw acc is exactly 0 for OOB (zfill halo), so ib=0 is safe
    }

#pragma unroll
    for (int dx = 0; dx < NS; dx++) {
        float4 o;
        o.x = acc[dx][0] * ia[0] * ib[dx + 0];
        o.y = acc[dx][1] * ia[1] * ib[dx + 1];
        o.z = acc[dx][2] * ia[2] * ib[dx + 2];
        o.w = acc[dx][3] * ia[3] * ib[dx + 3];
        const int q = dy * NS + dx;
        *(float4*)(out + ((size_t)(b * Qn + q) * Hn + y) * Wn + x0) = o;
    }
}

// ---------------------------------------------------------------------------
extern "C" void kernel_launch(void* const* d_in, const int* in_sizes, int n_in,
                              void* d_out, int out_size) {
    const float* fa = (const float*)d_in[0];
    const float* fb = (const float*)d_in[1];
    float* out = (float*)d_out;

    norm_kernel<<<dim3(HW / 256, Bn), 256>>>(fa, fb);

    cudaFuncSetAttribute(corr_kernel,
                         cudaFuncAttributeMaxDynamicSharedMemorySize,
                         SMEM_BYTES);
    corr_kernel<<<dim3(Hn / TY, Bn), NTHREADS, SMEM_BYTES>>>(fa, fb, out);
}

// round 8
// speedup vs baseline: 1.2789x; 1.1318x over previous
#include <cuda_runtime.h>
#include <cstdint>

// Problem constants
#define Bn 8
#define Cn 256
#define Hn 96
#define Wn 128
#define Dd 4
#define NS 9      // 2*D+1
#define Qn 81     // NS*NS
#define HW (Hn*Wn)

// Tiling: 2 rows per block; 576 consumer + 64 producer threads
#define TY 2
#define RX 4
#define XG (Wn/RX)            // 32
#define CONS (TY*XG*NS)       // 576 consumer threads (18 warps)
#define PROD 64               // 2 producer warps
#define NTHREADS (CONS+PROD)  // 640
#define CC 16
#define NCHUNK (Cn/CC)        // 16
#define FBW (Wn + 2*Dd)       // 136
#define FBH (TY + 2*Dd)       // 10
#define VW (RX + 2*Dd)        // 12

#define FA_FLOATS (CC*TY*Wn)          // 4096
#define FB_FLOATS (CC*FBH*FBW)        // 21760
#define STAGE_FLOATS (FA_FLOATS + FB_FLOATS)   // 25856
#define SMEM_BYTES (2*STAGE_FLOATS*4)          // 206848

// per-channel loader slots: fa 64, fb 340 -> 404 total
#define FA_SL (TY*(Wn/4))             // 64
#define FB_SL (FBH*(FBW/4))           // 340
#define TOT_SL (FA_SL+FB_SL)          // 404
#define PSL 7                         // ceil(404/64) slots per producer thread

// named barrier ids (0 reserved)
#define BFULL0 1
#define BFULL1 2
#define BEMPTY0 3
#define BEMPTY1 4

// Per-pixel inverse norms (scratch)
__device__ float g_inva[Bn*HW];
__device__ float g_invb[Bn*HW];

// ---------------------------------------------------------------------------
__device__ __forceinline__ void cp16(uint32_t saddr, const float* g, int nbytes) {
    asm volatile("cp.async.cg.shared.global [%0], [%1], 16, %2;"
                 :: "r"(saddr), "l"(g), "r"(nbytes));
}
__device__ __forceinline__ void bar_sync(int id) {
    asm volatile("bar.sync %0, %1;" :: "r"(id), "n"(NTHREADS) : "memory");
}
__device__ __forceinline__ void bar_arrive(int id) {
    asm volatile("bar.arrive %0, %1;" :: "r"(id), "n"(NTHREADS) : "memory");
}

// ---------------------------------------------------------------------------
// Pass 1: per-pixel inverse L2 norms (HBM-bound)
// ---------------------------------------------------------------------------
__global__ void norm_kernel(const float* __restrict__ fa,
                            const float* __restrict__ fb) {
    int pix = blockIdx.x * blockDim.x + threadIdx.x;
    int b   = blockIdx.y;
    const float* pa = fa + (size_t)b * Cn * HW + pix;
    const float* pb = fb + (size_t)b * Cn * HW + pix;
    float sa0 = 0.f, sa1 = 0.f, sb0 = 0.f, sb1 = 0.f;
#pragma unroll 8
    for (int c = 0; c < Cn; c += 2) {
        float va0 = pa[(size_t)c * HW], va1 = pa[(size_t)(c + 1) * HW];
        float vb0 = pb[(size_t)c * HW], vb1 = pb[(size_t)(c + 1) * HW];
        sa0 = fmaf(va0, va0, sa0); sa1 = fmaf(va1, va1, sa1);
        sb0 = fmaf(vb0, vb0, sb0); sb1 = fmaf(vb1, vb1, sb1);
    }
    g_inva[b * HW + pix] = 1.0f / fmaxf(sqrtf(sa0 + sa1), 1e-12f);
    g_invb[b * HW + pix] = 1.0f / fmaxf(sqrtf(sb0 + sb1), 1e-12f);
}

// ---------------------------------------------------------------------------
// Pass 2: warp-specialized correlation.
// Producers (2 warps): cp.async all slots, wait, bar.arrive(FULL).
// Consumers (18 warps): bar.sync(FULL) -> compute -> bar.arrive(EMPTY).
// ---------------------------------------------------------------------------
__global__ void __launch_bounds__(NTHREADS, 1)
corr_kernel(const float* __restrict__ fa,
            const float* __restrict__ fb,
            float* __restrict__ out) {
    extern __shared__ float smem[];

    const int b   = blockIdx.y;
    const int y0  = blockIdx.x * TY;
    const int tid = threadIdx.x;

    const size_t baseA = (size_t)b * Cn * HW;
    const uint32_t smem_u = (uint32_t)__cvta_generic_to_shared(smem);

    if (tid >= CONS) {
        // ================= PRODUCER =================
        const int ptid = tid - CONS;   // 0..63
        const float* ld_ptr[PSL];
        int ld_s[PSL], ld_str[PSL], ld_nb[PSL];
#pragma unroll
        for (int k = 0; k < PSL; k++) {
            int slot = ptid + k * PROD;
            ld_ptr[k] = nullptr; ld_s[k] = 0; ld_str[k] = 0; ld_nb[k] = -1;
            if (slot < TOT_SL) {
                if (slot < FA_SL) {
                    int yy = slot / (Wn / 4);
                    int x4 = slot % (Wn / 4);
                    ld_nb[k]  = 16;
                    ld_ptr[k] = fa + baseA + (y0 + yy) * Wn + x4 * 4;
                    ld_s[k]   = yy * Wn + x4 * 4;
                    ld_str[k] = TY * Wn;
                } else {
                    int u  = slot - FA_SL;
                    int hr = u / (FBW / 4);
                    int kk = u % (FBW / 4);
                    int yy = y0 - Dd + hr;
                    bool valid = (yy >= 0) && (yy < Hn) && (kk >= 1) && (kk <= Wn / 4);
                    ld_nb[k]  = valid ? 16 : 0;   // zfill halo/OOB
                    int yyc = min(max(yy, 0), Hn - 1);
                    int kc  = min(max(kk, 1), Wn / 4);
                    ld_ptr[k] = fb + baseA + yyc * Wn + kc * 4 - 4;
                    ld_s[k]   = FA_FLOATS + hr * FBW + kk * 4;
                    ld_str[k] = FBH * FBW;
                }
            }
        }

        int st = 0;
        for (int ch = 0; ch < NCHUNK; ch++) {
            bar_sync(BEMPTY0 + st);              // stage free?
            const int c0 = ch * CC;
            const uint32_t sb = smem_u + (uint32_t)(st * STAGE_FLOATS * 4);
#pragma unroll
            for (int k = 0; k < PSL; k++) {
                if (ld_nb[k] >= 0) {
                    const float* g = ld_ptr[k] + (size_t)c0 * HW;
                    const uint32_t sofs = sb + (uint32_t)(ld_s[k] * 4);
#pragma unroll
                    for (int cc = 0; cc < CC; cc++)
                        cp16(sofs + (uint32_t)(cc * ld_str[k] * 4),
                             g + (size_t)cc * HW, ld_nb[k]);
                }
            }
            asm volatile("cp.async.commit_group;");
            asm volatile("cp.async.wait_group 0;");
            bar_arrive(BFULL0 + st);             // stage ready
            st ^= 1;
        }
        return;
    }

    // ================= CONSUMER =================
    const int dy = tid / (TY * XG);          // 0..8 (uniform per warp)
    const int r  = tid % (TY * XG);
    const int yl = r / XG;                   // 0..1
    const int xg = r % XG;                   // 0..31
    const int x0 = xg * RX;

    float acc[NS][RX];
#pragma unroll
    for (int d = 0; d < NS; d++)
#pragma unroll
        for (int i = 0; i < RX; i++) acc[d][i] = 0.f;

    const int ofsA = yl * Wn + x0;
    const int ofsB = (yl + dy) * FBW + x0;

    // pre-arm both EMPTY barriers so the producer can run 2 chunks ahead
    bar_arrive(BEMPTY0);
    bar_arrive(BEMPTY1);

    int st = 0;
    for (int ch = 0; ch < NCHUNK; ch++) {
        bar_sync(BFULL0 + st);                // wait for stage data

        const float* s_fa = smem + st * STAGE_FLOATS;
        const float* s_fb = s_fa + FA_FLOATS;

        // register double-buffer across channels
        float4 A, V0, V1, V2;
        A  = *(const float4*)(s_fa + ofsA);
        V0 = *(const float4*)(s_fb + ofsB);
        V1 = *(const float4*)(s_fb + ofsB + 4);
        V2 = *(const float4*)(s_fb + ofsB + 8);

#pragma unroll
        for (int cc = 0; cc < CC; cc++) {
            float4 An, V0n, V1n, V2n;
            if (cc + 1 < CC) {
                const float* fap = s_fa + (cc + 1) * (TY * Wn) + ofsA;
                const float* fbp = s_fb + (cc + 1) * (FBH * FBW) + ofsB;
                An  = *(const float4*)(fap);
                V0n = *(const float4*)(fbp);
                V1n = *(const float4*)(fbp + 4);
                V2n = *(const float4*)(fbp + 8);
            }
            float a[RX] = {A.x, A.y, A.z, A.w};
            float v[VW] = {V0.x, V0.y, V0.z, V0.w, V1.x, V1.y, V1.z, V1.w,
                           V2.x, V2.y, V2.z, V2.w};
#pragma unroll
            for (int dx = 0; dx < NS; dx++)
#pragma unroll
                for (int i = 0; i < RX; i++)
                    acc[dx][i] = fmaf(a[i], v[dx + i], acc[dx][i]);
            if (cc + 1 < CC) { A = An; V0 = V0n; V1 = V1n; V2 = V2n; }
        }
        bar_arrive(BEMPTY0 + st);             // stage consumed
        st ^= 1;
    }

    // ---- epilogue: scale by inverse norms, write float4 per dx ----
    const int y = y0 + yl;
    float ia[RX];
#pragma unroll
    for (int i = 0; i < RX; i++) ia[i] = g_inva[b * HW + y * Wn + x0 + i];

    const int sy = y + dy - Dd;
    const bool rowok = (unsigned)sy < (unsigned)Hn;
    float ib[VW];
#pragma unroll
    for (int k = 0; k < VW; k++) {
        int sx = x0 + k - Dd;
        ib[k] = (rowok && (unsigned)sx < (unsigned)Wn)
                    ? g_invb[b * HW + sy * Wn + sx] : 0.f;
        // raw acc is exactly 0 for OOB (zfill halo), so ib=0 is safe
    }

#pragma unroll
    for (int dx = 0; dx < NS; dx++) {
        float4 o;
        o.x = acc[dx][0] * ia[0] * ib[dx + 0];
        o.y = acc[dx][1] * ia[1] * ib[dx + 1];
        o.z = acc[dx][2] * ia[2] * ib[dx + 2];
        o.w = acc[dx][3] * ia[3] * ib[dx + 3];
        const int q = dy * NS + dx;
        *(float4*)(out + ((size_t)(b * Qn + q) * Hn + y) * Wn + x0) = o;
    }
}

// ---------------------------------------------------------------------------
extern "C" void kernel_launch(void* const* d_in, const int* in_sizes, int n_in,
                              void* d_out, int out_size) {
    const float* fa = (const float*)d_in[0];
    const float* fb = (const float*)d_in[1];
    float* out = (float*)d_out;

    norm_kernel<<<dim3(HW / 256, Bn), 256>>>(fa, fb);

    cudaFuncSetAttribute(corr_kernel,
                         cudaFuncAttributeMaxDynamicSharedMemorySize,
                         SMEM_BYTES);
    corr_kernel<<<dim3(Hn / TY, Bn), NTHREADS, SMEM_BYTES>>>(fa, fb, out);
}

// round 9
// speedup vs baseline: 1.4470x; 1.1314x over previous
#include <cuda_runtime.h>
#include <cstdint>

// Problem constants
#define Bn 8
#define Cn 256
#define Hn 96
#define Wn 128
#define Dd 4
#define NS 9      // 2*D+1
#define Qn 81     // NS*NS
#define HW (Hn*Wn)

// Tiling: 2 rows per block; RX=8; 288 consumer + 64 producer threads
#define TY 2
#define RX 8
#define XG (Wn/RX)            // 16
#define CONS (TY*XG*NS)       // 288 consumer threads (9 warps)
#define PROD 64               // 2 producer warps
#define NTHREADS (CONS+PROD)  // 352
#define CC 16
#define NCHUNK (Cn/CC)        // 16
#define FBW (Wn + 2*Dd)       // 136
#define FBH (TY + 2*Dd)       // 10
#define VW (RX + 2*Dd)        // 16 window floats per thread

#define FA_FLOATS (CC*TY*Wn)          // 4096
#define FB_FLOATS (CC*FBH*FBW)        // 21760
#define STAGE_FLOATS (FA_FLOATS + FB_FLOATS)   // 25856
#define SMEM_BYTES (2*STAGE_FLOATS*4)          // 206848

// per-channel loader slots: fa 64, fb 340 -> 404 total
#define FA_SL (TY*(Wn/4))             // 64
#define FB_SL (FBH*(FBW/4))           // 340
#define TOT_SL (FA_SL+FB_SL)          // 404
#define PSL 7                         // ceil(404/64)

// named barrier ids (0 reserved)
#define BFULL0 1
#define BFULL1 2
#define BEMPTY0 3
#define BEMPTY1 4

// Per-pixel inverse norms (scratch)
__device__ float g_inva[Bn*HW];
__device__ float g_invb[Bn*HW];

// bank-quad swizzle on 16B-unit index within a row:
// makes 32B-stride lane patterns conflict-free for LDS.128
__device__ __host__ __forceinline__ int sw(int u) { return u ^ ((u >> 3) & 1); }

// ---------------------------------------------------------------------------
__device__ __forceinline__ void cp16(uint32_t saddr, const float* g, int nbytes) {
    asm volatile("cp.async.cg.shared.global [%0], [%1], 16, %2;"
                 :: "r"(saddr), "l"(g), "r"(nbytes));
}
__device__ __forceinline__ void bar_sync(int id) {
    asm volatile("bar.sync %0, %1;" :: "r"(id), "n"(NTHREADS) : "memory");
}
__device__ __forceinline__ void bar_arrive(int id) {
    asm volatile("bar.arrive %0, %1;" :: "r"(id), "n"(NTHREADS) : "memory");
}

// ---------------------------------------------------------------------------
// Pass 1: per-pixel inverse L2 norms (HBM-bound)
// ---------------------------------------------------------------------------
__global__ void norm_kernel(const float* __restrict__ fa,
                            const float* __restrict__ fb) {
    int pix = blockIdx.x * blockDim.x + threadIdx.x;
    int b   = blockIdx.y;
    const float* pa = fa + (size_t)b * Cn * HW + pix;
    const float* pb = fb + (size_t)b * Cn * HW + pix;
    float sa0 = 0.f, sa1 = 0.f, sb0 = 0.f, sb1 = 0.f;
#pragma unroll 8
    for (int c = 0; c < Cn; c += 2) {
        float va0 = pa[(size_t)c * HW], va1 = pa[(size_t)(c + 1) * HW];
        float vb0 = pb[(size_t)c * HW], vb1 = pb[(size_t)(c + 1) * HW];
        sa0 = fmaf(va0, va0, sa0); sa1 = fmaf(va1, va1, sa1);
        sb0 = fmaf(vb0, vb0, sb0); sb1 = fmaf(vb1, vb1, sb1);
    }
    g_inva[b * HW + pix] = 1.0f / fmaxf(sqrtf(sa0 + sa1), 1e-12f);
    g_invb[b * HW + pix] = 1.0f / fmaxf(sqrtf(sb0 + sb1), 1e-12f);
}

// ---------------------------------------------------------------------------
// Pass 2: warp-specialized correlation, RX=8, swizzled smem.
// Consumers: 9 warps, thread = (yl, 8 x-pixels, dy=warp) -> 72 acc.
// Per channel: 2 LDS.128 fa + 4 LDS.128 fb -> 72 FFMA (ratio 3.0).
// ---------------------------------------------------------------------------
__global__ void __launch_bounds__(NTHREADS, 1)
corr_kernel(const float* __restrict__ fa,
            const float* __restrict__ fb,
            float* __restrict__ out) {
    extern __shared__ float smem[];

    const int b   = blockIdx.y;
    const int y0  = blockIdx.x * TY;
    const int tid = threadIdx.x;

    const size_t baseA = (size_t)b * Cn * HW;
    const uint32_t smem_u = (uint32_t)__cvta_generic_to_shared(smem);

    if (tid >= CONS) {
        // ================= PRODUCER =================
        const int ptid = tid - CONS;   // 0..63
        const float* ld_ptr[PSL];
        int ld_s[PSL], ld_str[PSL], ld_nb[PSL];
#pragma unroll
        for (int k = 0; k < PSL; k++) {
            int slot = ptid + k * PROD;
            ld_ptr[k] = nullptr; ld_s[k] = 0; ld_str[k] = 0; ld_nb[k] = -1;
            if (slot < TOT_SL) {
                if (slot < FA_SL) {
                    int yy = slot / (Wn / 4);
                    int u  = slot % (Wn / 4);
                    ld_nb[k]  = 16;
                    ld_ptr[k] = fa + baseA + (y0 + yy) * Wn + u * 4;
                    ld_s[k]   = yy * Wn + sw(u) * 4;
                    ld_str[k] = TY * Wn;
                } else {
                    int u  = slot - FA_SL;
                    int hr = u / (FBW / 4);
                    int kk = u % (FBW / 4);
                    int yy = y0 - Dd + hr;
                    bool valid = (yy >= 0) && (yy < Hn) && (kk >= 1) && (kk <= Wn / 4);
                    ld_nb[k]  = valid ? 16 : 0;   // zfill halo/OOB
                    int yyc = min(max(yy, 0), Hn - 1);
                    int kc  = min(max(kk, 1), Wn / 4);
                    ld_ptr[k] = fb + baseA + yyc * Wn + kc * 4 - 4;
                    ld_s[k]   = FA_FLOATS + hr * FBW + sw(kk) * 4;
                    ld_str[k] = FBH * FBW;
                }
            }
        }

        int st = 0;
        for (int ch = 0; ch < NCHUNK; ch++) {
            bar_sync(BEMPTY0 + st);
            const int c0 = ch * CC;
            const uint32_t sb = smem_u + (uint32_t)(st * STAGE_FLOATS * 4);
#pragma unroll
            for (int k = 0; k < PSL; k++) {
                if (ld_nb[k] >= 0) {
                    const float* g = ld_ptr[k] + (size_t)c0 * HW;
                    const uint32_t sofs = sb + (uint32_t)(ld_s[k] * 4);
#pragma unroll
                    for (int cc = 0; cc < CC; cc++)
                        cp16(sofs + (uint32_t)(cc * ld_str[k] * 4),
                             g + (size_t)cc * HW, ld_nb[k]);
                }
            }
            asm volatile("cp.async.commit_group;");
            asm volatile("cp.async.wait_group 0;");
            bar_arrive(BFULL0 + st);
            st ^= 1;
        }
        return;
    }

    // ================= CONSUMER =================
    const int dy = tid / 32;                 // 0..8 (one dy per warp)
    const int r  = tid % 32;
    const int yl = r / XG;                   // 0..1
    const int xg = r % XG;                   // 0..15
    const int x0 = xg * RX;

    // swizzled, channel-invariant float offsets
    int faO[2], fbO[4];
#pragma unroll
    for (int j = 0; j < 2; j++)
        faO[j] = yl * Wn + sw(2 * xg + j) * 4;
#pragma unroll
    for (int j = 0; j < 4; j++)
        fbO[j] = (yl + dy) * FBW + sw(2 * xg + j) * 4;

    float acc[NS][RX];
#pragma unroll
    for (int d = 0; d < NS; d++)
#pragma unroll
        for (int i = 0; i < RX; i++) acc[d][i] = 0.f;

    bar_arrive(BEMPTY0);
    bar_arrive(BEMPTY1);

    int st = 0;
    for (int ch = 0; ch < NCHUNK; ch++) {
        bar_sync(BFULL0 + st);

        const float* s_fa = smem + st * STAGE_FLOATS;
        const float* s_fb = s_fa + FA_FLOATS;

        // register double-buffer across channels
        float4 A0, A1, V0, V1, V2, V3;
        A0 = *(const float4*)(s_fa + faO[0]);
        A1 = *(const float4*)(s_fa + faO[1]);
        V0 = *(const float4*)(s_fb + fbO[0]);
        V1 = *(const float4*)(s_fb + fbO[1]);
        V2 = *(const float4*)(s_fb + fbO[2]);
        V3 = *(const float4*)(s_fb + fbO[3]);

#pragma unroll
        for (int cc = 0; cc < CC; cc++) {
            float4 A0n, A1n, V0n, V1n, V2n, V3n;
            if (cc + 1 < CC) {
                const float* fap = s_fa + (cc + 1) * (TY * Wn);
                const float* fbp = s_fb + (cc + 1) * (FBH * FBW);
                A0n = *(const float4*)(fap + faO[0]);
                A1n = *(const float4*)(fap + faO[1]);
                V0n = *(const float4*)(fbp + fbO[0]);
                V1n = *(const float4*)(fbp + fbO[1]);
                V2n = *(const float4*)(fbp + fbO[2]);
                V3n = *(const float4*)(fbp + fbO[3]);
            }
            float a[RX] = {A0.x, A0.y, A0.z, A0.w, A1.x, A1.y, A1.z, A1.w};
            float v[VW] = {V0.x, V0.y, V0.z, V0.w, V1.x, V1.y, V1.z, V1.w,
                           V2.x, V2.y, V2.z, V2.w, V3.x, V3.y, V3.z, V3.w};
#pragma unroll
            for (int dx = 0; dx < NS; dx++)
#pragma unroll
                for (int i = 0; i < RX; i++)
                    acc[dx][i] = fmaf(a[i], v[dx + i], acc[dx][i]);
            if (cc + 1 < CC) {
                A0 = A0n; A1 = A1n; V0 = V0n; V1 = V1n; V2 = V2n; V3 = V3n;
            }
        }
        bar_arrive(BEMPTY0 + st);
        st ^= 1;
    }

    // ---- epilogue: scale by inverse norms, write 2x float4 per dx ----
    const int y = y0 + yl;
    float ia[RX];
#pragma unroll
    for (int i = 0; i < RX; i++) ia[i] = g_inva[b * HW + y * Wn + x0 + i];

    const int sy = y + dy - Dd;
    const bool rowok = (unsigned)sy < (unsigned)Hn;
    float ib[VW];
#pragma unroll
    for (int k = 0; k < VW; k++) {
        int sx = x0 + k - Dd;
        ib[k] = (rowok && (unsigned)sx < (unsigned)Wn)
                    ? g_invb[b * HW + sy * Wn + sx] : 0.f;
        // raw acc is exactly 0 for OOB (zfill halo), so ib=0 is safe
    }

#pragma unroll
    for (int dx = 0; dx < NS; dx++) {
        float o[RX];
#pragma unroll
        for (int i = 0; i < RX; i++)
            o[i] = acc[dx][i] * ia[i] * ib[dx + i];
        const int q = dy * NS + dx;
        float* op = out + ((size_t)(b * Qn + q) * Hn + y) * Wn + x0;
        *(float4*)(op)     = make_float4(o[0], o[1], o[2], o[3]);
        *(float4*)(op + 4) = make_float4(o[4], o[5], o[6], o[7]);
    }
}

// ---------------------------------------------------------------------------
extern "C" void kernel_launch(void* const* d_in, const int* in_sizes, int n_in,
                              void* d_out, int out_size) {
    const float* fa = (const float*)d_in[0];
    const float* fb = (const float*)d_in[1];
    float* out = (float*)d_out;

    norm_kernel<<<dim3(HW / 256, Bn), 256>>>(fa, fb);

    cudaFuncSetAttribute(corr_kernel,
                         cudaFuncAttributeMaxDynamicSharedMemorySize,
                         SMEM_BYTES);
    corr_kernel<<<dim3(Hn / TY, Bn), NTHREADS, SMEM_BYTES>>>(fa, fb, out);
}

// round 10
// speedup vs baseline: 1.4990x; 1.0359x over previous
#include <cuda_runtime.h>
#include <cstdint>

// Problem constants
#define Bn 8
#define Cn 256
#define Hn 96
#define Wn 128
#define Dd 4
#define NS 9      // 2*D+1
#define Qn 81     // NS*NS
#define HW (Hn*Wn)

// Tiling: 2 rows per block; RX=8; 288 consumer + 64 producer threads
#define TY 2
#define RX 8
#define XG (Wn/RX)            // 16
#define CONS (TY*XG*NS)       // 288 consumer threads (9 warps)
#define PROD 64               // 2 producer warps
#define NTHREADS (CONS+PROD)  // 352
#define CC 16
#define NCHUNK (Cn/CC)        // 16
#define FBW (Wn + 2*Dd)       // 136
#define FBH (TY + 2*Dd)       // 10
#define VW (RX + 2*Dd)        // 16 window floats per thread

#define FA_FLOATS (CC*TY*Wn)          // 4096
#define FB_FLOATS (CC*FBH*FBW)        // 21760
#define STAGE_FLOATS (FA_FLOATS + FB_FLOATS)   // 25856
#define NORM_FLOATS (TY*Wn)           // 256 (inva tile)
#define SMEM_BYTES ((2*STAGE_FLOATS + NORM_FLOATS)*4)  // 207872

// per-channel loader slots: fa 64, fb 340 -> 404 total
#define FA_SL (TY*(Wn/4))             // 64 (== PROD: one fa slot per producer)
#define FB_SL (FBH*(FBW/4))           // 340
#define TOT_SL (FA_SL+FB_SL)          // 404
#define PSL 7                         // ceil(404/64)

// named barrier ids (0 reserved)
#define BFULL0 1
#define BFULL1 2
#define BEMPTY0 3
#define BEMPTY1 4
#define BNORM 5

// Per-pixel inverse norms for fb (scratch)
__device__ float g_invb[Bn*HW];

// bank-quad swizzle on 16B-unit index within a row
__device__ __host__ __forceinline__ int sw(int u) { return u ^ ((u >> 3) & 1); }

// ---------------------------------------------------------------------------
__device__ __forceinline__ void cp16(uint32_t saddr, const float* g, int nbytes) {
    asm volatile("cp.async.cg.shared.global [%0], [%1], 16, %2;"
                 :: "r"(saddr), "l"(g), "r"(nbytes));
}
__device__ __forceinline__ void bar_sync(int id) {
    asm volatile("bar.sync %0, %1;" :: "r"(id), "n"(NTHREADS) : "memory");
}
__device__ __forceinline__ void bar_arrive(int id) {
    asm volatile("bar.arrive %0, %1;" :: "r"(id), "n"(NTHREADS) : "memory");
}

// ---------------------------------------------------------------------------
// Pass 1: per-pixel inverse L2 norms for fb ONLY (fa norms folded into corr).
// float2 loads, 128 threads, 384 blocks.
// ---------------------------------------------------------------------------
__global__ void norm_b_kernel(const float* __restrict__ fb) {
    int p2 = blockIdx.x * blockDim.x + threadIdx.x;   // float2 index
    int b  = blockIdx.y;
    const float2* pb = (const float2*)(fb + (size_t)b * Cn * HW) + p2;
    float s0 = 0.f, s1 = 0.f;
#pragma unroll 8
    for (int c = 0; c < Cn; c++) {
        float2 v = pb[(size_t)c * (HW / 2)];
        s0 = fmaf(v.x, v.x, s0);
        s1 = fmaf(v.y, v.y, s1);
    }
    float2 o;
    o.x = 1.0f / fmaxf(sqrtf(s0), 1e-12f);
    o.y = 1.0f / fmaxf(sqrtf(s1), 1e-12f);
    ((float2*)g_invb)[b * (HW / 2) + p2] = o;
}

// ---------------------------------------------------------------------------
// Pass 2: warp-specialized correlation, RX=8, swizzled smem.
// Producers additionally accumulate fa^2 (their own loaded slots) -> inva
// in smem; consumers read it in the epilogue after a split-phase barrier.
// ---------------------------------------------------------------------------
__global__ void __launch_bounds__(NTHREADS, 1)
corr_kernel(const float* __restrict__ fa,
            const float* __restrict__ fb,
            float* __restrict__ out) {
    extern __shared__ float smem[];

    const int b   = blockIdx.y;
    const int y0  = blockIdx.x * TY;
    const int tid = threadIdx.x;

    const size_t baseA = (size_t)b * Cn * HW;
    const uint32_t smem_u = (uint32_t)__cvta_generic_to_shared(smem);
    float* s_norm = smem + 2 * STAGE_FLOATS;   // inva tile [TY*Wn]

    if (tid >= CONS) {
        // ================= PRODUCER =================
        const int ptid = tid - CONS;   // 0..63
        const float* ld_ptr[PSL];
        int ld_s[PSL], ld_str[PSL], ld_nb[PSL];
#pragma unroll
        for (int k = 0; k < PSL; k++) {
            int slot = ptid + k * PROD;
            ld_ptr[k] = nullptr; ld_s[k] = 0; ld_str[k] = 0; ld_nb[k] = -1;
            if (slot < TOT_SL) {
                if (slot < FA_SL) {
                    int yy = slot / (Wn / 4);
                    int u  = slot % (Wn / 4);
                    ld_nb[k]  = 16;
                    ld_ptr[k] = fa + baseA + (y0 + yy) * Wn + u * 4;
                    ld_s[k]   = yy * Wn + sw(u) * 4;
                    ld_str[k] = TY * Wn;
                } else {
                    int u  = slot - FA_SL;
                    int hr = u / (FBW / 4);
                    int kk = u % (FBW / 4);
                    int yy = y0 - Dd + hr;
                    bool valid = (yy >= 0) && (yy < Hn) && (kk >= 1) && (kk <= Wn / 4);
                    ld_nb[k]  = valid ? 16 : 0;   // zfill halo/OOB
                    int yyc = min(max(yy, 0), Hn - 1);
                    int kc  = min(max(kk, 1), Wn / 4);
                    ld_ptr[k] = fb + baseA + yyc * Wn + kc * 4 - 4;
                    ld_s[k]   = FA_FLOATS + hr * FBW + sw(kk) * 4;
                    ld_str[k] = FBH * FBW;
                }
            }
        }

        // this producer's own fa slot (exactly one: slot == ptid)
        const int fa_yy = ptid / (Wn / 4);
        const int fa_u  = ptid % (Wn / 4);
        const int fa_sofs = fa_yy * Wn + sw(fa_u) * 4;   // smem float offset
        float sq[4] = {0.f, 0.f, 0.f, 0.f};

        int st = 0;
        for (int ch = 0; ch < NCHUNK; ch++) {
            bar_sync(BEMPTY0 + st);
            const int c0 = ch * CC;
            const uint32_t sb = smem_u + (uint32_t)(st * STAGE_FLOATS * 4);
#pragma unroll
            for (int k = 0; k < PSL; k++) {
                if (ld_nb[k] >= 0) {
                    const float* g = ld_ptr[k] + (size_t)c0 * HW;
                    const uint32_t sofs = sb + (uint32_t)(ld_s[k] * 4);
#pragma unroll
                    for (int cc = 0; cc < CC; cc++)
                        cp16(sofs + (uint32_t)(cc * ld_str[k] * 4),
                             g + (size_t)cc * HW, ld_nb[k]);
                }
            }
            asm volatile("cp.async.commit_group;");
            asm volatile("cp.async.wait_group 0;");
            bar_arrive(BFULL0 + st);

            // fa^2 accumulation on this thread's OWN slot (visible after wait)
            const float* sfa = smem + st * STAGE_FLOATS + fa_sofs;
#pragma unroll
            for (int cc = 0; cc < CC; cc++) {
                float4 v = *(const float4*)(sfa + cc * (TY * Wn));
                sq[0] = fmaf(v.x, v.x, sq[0]);
                sq[1] = fmaf(v.y, v.y, sq[1]);
                sq[2] = fmaf(v.z, v.z, sq[2]);
                sq[3] = fmaf(v.w, v.w, sq[3]);
            }
            st ^= 1;
        }

        // publish inva for this thread's 4 pixels
        float4 iv;
        iv.x = 1.0f / fmaxf(sqrtf(sq[0]), 1e-12f);
        iv.y = 1.0f / fmaxf(sqrtf(sq[1]), 1e-12f);
        iv.z = 1.0f / fmaxf(sqrtf(sq[2]), 1e-12f);
        iv.w = 1.0f / fmaxf(sqrtf(sq[3]), 1e-12f);
        *(float4*)(s_norm + fa_yy * Wn + fa_u * 4) = iv;
        bar_arrive(BNORM);
        return;
    }

    // ================= CONSUMER =================
    const int dy = tid / 32;                 // 0..8 (one dy per warp)
    const int r  = tid % 32;
    const int yl = r / XG;                   // 0..1
    const int xg = r % XG;                   // 0..15
    const int x0 = xg * RX;

    // swizzled, channel-invariant float offsets
    int faO[2], fbO[4];
#pragma unroll
    for (int j = 0; j < 2; j++)
        faO[j] = yl * Wn + sw(2 * xg + j) * 4;
#pragma unroll
    for (int j = 0; j < 4; j++)
        fbO[j] = (yl + dy) * FBW + sw(2 * xg + j) * 4;

    float acc[NS][RX];
#pragma unroll
    for (int d = 0; d < NS; d++)
#pragma unroll
        for (int i = 0; i < RX; i++) acc[d][i] = 0.f;

    bar_arrive(BEMPTY0);
    bar_arrive(BEMPTY1);

    int st = 0;
    for (int ch = 0; ch < NCHUNK; ch++) {
        bar_sync(BFULL0 + st);

        const float* s_fa = smem + st * STAGE_FLOATS;
        const float* s_fb = s_fa + FA_FLOATS;

        // register double-buffer across channels
        float4 A0, A1, V0, V1, V2, V3;
        A0 = *(const float4*)(s_fa + faO[0]);
        A1 = *(const float4*)(s_fa + faO[1]);
        V0 = *(const float4*)(s_fb + fbO[0]);
        V1 = *(const float4*)(s_fb + fbO[1]);
        V2 = *(const float4*)(s_fb + fbO[2]);
        V3 = *(const float4*)(s_fb + fbO[3]);

#pragma unroll
        for (int cc = 0; cc < CC; cc++) {
            float4 A0n, A1n, V0n, V1n, V2n, V3n;
            if (cc + 1 < CC) {
                const float* fap = s_fa + (cc + 1) * (TY * Wn);
                const float* fbp = s_fb + (cc + 1) * (FBH * FBW);
                A0n = *(const float4*)(fap + faO[0]);
                A1n = *(const float4*)(fap + faO[1]);
                V0n = *(const float4*)(fbp + fbO[0]);
                V1n = *(const float4*)(fbp + fbO[1]);
                V2n = *(const float4*)(fbp + fbO[2]);
                V3n = *(const float4*)(fbp + fbO[3]);
            }
            float a[RX] = {A0.x, A0.y, A0.z, A0.w, A1.x, A1.y, A1.z, A1.w};
            float v[VW] = {V0.x, V0.y, V0.z, V0.w, V1.x, V1.y, V1.z, V1.w,
                           V2.x, V2.y, V2.z, V2.w, V3.x, V3.y, V3.z, V3.w};
#pragma unroll
            for (int dx = 0; dx < NS; dx++)
#pragma unroll
                for (int i = 0; i < RX; i++)
                    acc[dx][i] = fmaf(a[i], v[dx + i], acc[dx][i]);
            if (cc + 1 < CC) {
                A0 = A0n; A1 = A1n; V0 = V0n; V1 = V1n; V2 = V2n; V3 = V3n;
            }
        }
        bar_arrive(BEMPTY0 + st);
        st ^= 1;
    }

    // wait for producers to publish inva
    bar_sync(BNORM);

    // ---- epilogue: scale by inverse norms, write 2x float4 per dx ----
    const int y = y0 + yl;
    float ia[RX];
#pragma unroll
    for (int i = 0; i < RX; i++) ia[i] = s_norm[yl * Wn + x0 + i];

    const int sy = y + dy - Dd;
    const bool rowok = (unsigned)sy < (unsigned)Hn;
    float ib[VW];
#pragma unroll
    for (int k = 0; k < VW; k++) {
        int sx = x0 + k - Dd;
        ib[k] = (rowok && (unsigned)sx < (unsigned)Wn)
                    ? g_invb[b * HW + sy * Wn + sx] : 0.f;
        // raw acc is exactly 0 for OOB (zfill halo), so ib=0 is safe
    }

#pragma unroll
    for (int dx = 0; dx < NS; dx++) {
        float o[RX];
#pragma unroll
        for (int i = 0; i < RX; i++)
            o[i] = acc[dx][i] * ia[i] * ib[dx + i];
        const int q = dy * NS + dx;
        float* op = out + ((size_t)(b * Qn + q) * Hn + y) * Wn + x0;
        *(float4*)(op)     = make_float4(o[0], o[1], o[2], o[3]);
        *(float4*)(op + 4) = make_float4(o[4], o[5], o[6], o[7]);
    }
}

// ---------------------------------------------------------------------------
extern "C" void kernel_launch(void* const* d_in, const int* in_sizes, int n_in,
                              void* d_out, int out_size) {
    const float* fa = (const float*)d_in[0];
    const float* fb = (const float*)d_in[1];
    float* out = (float*)d_out;

    norm_b_kernel<<<dim3(HW / 2 / 128, Bn), 128>>>(fb);

    cudaFuncSetAttribute(corr_kernel,
                         cudaFuncAttributeMaxDynamicSharedMemorySize,
                         SMEM_BYTES);
    corr_kernel<<<dim3(Hn / TY, Bn), NTHREADS, SMEM_BYTES>>>(fa, fb, out);
}